// round 4
// baseline (speedup 1.0000x reference)
#include <cuda_runtime.h>
#include <math.h>

// Shapes
#define BATCH 64
#define TT    50
#define VOC   32000
#define EDIM  64
#define DH    128
#define NH    8
#define MDIM  256
#define NTOK  (BATCH*TT)      // 3200
#define HD    (NH*DH)         // 1024

// ---------------------------------------------------------------------------
// Scratch (no allocations allowed -> __device__ globals)
// ---------------------------------------------------------------------------
__device__ float g_h[NTOK*EDIM];
__device__ float g_Q[NTOK*HD];
__device__ float g_K[NTOK*HD];
__device__ float g_V[NTOK*HD];
__device__ float g_O[NTOK*HD];
__device__ float g_a[NTOK*EDIM];
__device__ float g_m[NTOK*MDIM];
__device__ float g_y[NTOK*EDIM];

// ---------------------------------------------------------------------------
// f32x2 packed math (sm_103a FFMA2: 2 fp32 FMAs per issue slot)
// ---------------------------------------------------------------------------
__device__ __forceinline__ unsigned long long pack2(float x, float y) {
    unsigned long long r;
    asm("mov.b64 %0, {%1, %2};" : "=l"(r) : "f"(x), "f"(y));
    return r;
}
__device__ __forceinline__ float2 unpack2(unsigned long long v) {
    float2 r;
    asm("mov.b64 {%0, %1}, %2;" : "=f"(r.x), "=f"(r.y) : "l"(v));
    return r;
}
__device__ __forceinline__ void ffma2(unsigned long long& d,
                                      unsigned long long a,
                                      unsigned long long b) {
    asm("fma.rn.f32x2 %0, %1, %2, %0;" : "+l"(d) : "l"(a), "l"(b));
}

__device__ __forceinline__ float act_apply(float v, int act) {
    if (act == 1) {
        // exact GELU: 0.5*x*(1+erf(x/sqrt(2)))
        v = 0.5f * v * (1.0f + erff(v * 0.70710678118654752f));
    }
    return v;
}

// ---------------------------------------------------------------------------
// Tile GEMM core: computes a 64(M) x 64(N) tile of C = A*B + bias, act.
//   A: row-major, points at (row m0, col 0), leading dim lda, K columns.
//   B: row-major, points at (row 0, col n0-of-tile), leading dim ldb.
//   bias: points at tile's first column.  C: points at (m0, n0).
// 256 threads, 4x4 micro-tile per thread, f32x2 accumulators.
// K must be a multiple of 64.
// ---------------------------------------------------------------------------
__device__ void gemm64_core(const float* __restrict__ A, int lda,
                            const float* __restrict__ B, int ldb,
                            const float* __restrict__ bias,
                            float* __restrict__ C, int ldc,
                            int K, int act) {
    __shared__ float As[64][68];   // [m][k], padded: conflict-free scalar reads
    __shared__ float Bs[64][64];   // [k][n]

    const int tid = threadIdx.x;
    const int tn  = (tid & 15) * 4;   // n within tile
    const int tm  = (tid >> 4) * 4;   // m within tile

    unsigned long long acc[4][2];
#pragma unroll
    for (int i = 0; i < 4; i++) { acc[i][0] = 0ull; acc[i][1] = 0ull; }

    for (int k0 = 0; k0 < K; k0 += 64) {
        // Load A chunk (64 rows x 64 k) vectorized along k
#pragma unroll
        for (int i = 0; i < 4; i++) {
            int idx = i * 256 + tid;
            int r = idx >> 4;            // m row 0..63
            int c = (idx & 15) * 4;      // k col (float4)
            float4 v = *(const float4*)(A + r * lda + k0 + c);
            *(float4*)&As[r][c] = v;
        }
        // Load B chunk (64 k x 64 n) vectorized along n
#pragma unroll
        for (int i = 0; i < 4; i++) {
            int idx = i * 256 + tid;
            int r = idx >> 4;            // k row 0..63
            int c = (idx & 15) * 4;      // n col (float4)
            float4 v = *(const float4*)(B + (long long)(k0 + r) * ldb + c);
            *(float4*)&Bs[r][c] = v;
        }
        __syncthreads();

#pragma unroll 8
        for (int k = 0; k < 64; k++) {
            float a0 = As[tm + 0][k];
            float a1 = As[tm + 1][k];
            float a2 = As[tm + 2][k];
            float a3 = As[tm + 3][k];
            float4 b4 = *(const float4*)&Bs[k][tn];
            unsigned long long b01 = pack2(b4.x, b4.y);
            unsigned long long b23 = pack2(b4.z, b4.w);
            unsigned long long aa;
            aa = pack2(a0, a0); ffma2(acc[0][0], aa, b01); ffma2(acc[0][1], aa, b23);
            aa = pack2(a1, a1); ffma2(acc[1][0], aa, b01); ffma2(acc[1][1], aa, b23);
            aa = pack2(a2, a2); ffma2(acc[2][0], aa, b01); ffma2(acc[2][1], aa, b23);
            aa = pack2(a3, a3); ffma2(acc[3][0], aa, b01); ffma2(acc[3][1], aa, b23);
        }
        __syncthreads();
    }

    float4 bv4 = *(const float4*)(bias + tn);
#pragma unroll
    for (int i = 0; i < 4; i++) {
        float2 p0 = unpack2(acc[i][0]);
        float2 p1 = unpack2(acc[i][1]);
        float4 o;
        o.x = act_apply(p0.x + bv4.x, act);
        o.y = act_apply(p0.y + bv4.y, act);
        o.z = act_apply(p1.x + bv4.z, act);
        o.w = act_apply(p1.y + bv4.w, act);
        *(float4*)(C + (long long)(tm + i) * ldc + tn) = o;
    }
}

// ---------------------------------------------------------------------------
// Kernels
// ---------------------------------------------------------------------------
__global__ void embed_kernel(const int* __restrict__ x,
                             const float* __restrict__ tok,
                             const float* __restrict__ pos) {
    int i = blockIdx.x * 256 + threadIdx.x;
    if (i >= NTOK * EDIM) return;
    int m = i >> 6;          // token
    int e = i & 63;
    int t = m % TT;
    int id = x[m];
    g_h[i] = tok[id * EDIM + e] + pos[t * EDIM + e];
}

// grid: (50, 16, 3)  y = head*2 + dtile, z selects Q/K/V
__global__ void qkv_kernel(const float* __restrict__ Wq, const float* __restrict__ bq,
                           const float* __restrict__ Wk, const float* __restrict__ bk,
                           const float* __restrict__ Wv, const float* __restrict__ bv) {
    int m0   = blockIdx.x * 64;
    int head = blockIdx.y >> 1;
    int dt   = blockIdx.y & 1;
    const float* W; const float* bb; float* C;
    if (blockIdx.z == 0)      { W = Wq; bb = bq; C = g_Q; }
    else if (blockIdx.z == 1) { W = Wk; bb = bk; C = g_K; }
    else                      { W = Wv; bb = bv; C = g_V; }
    int n0 = head * DH + dt * 64;
    gemm64_core(g_h + (long long)m0 * EDIM, EDIM,
                W + head * EDIM * DH + dt * 64, DH,
                bb + n0,
                C + (long long)m0 * HD + n0, HD,
                EDIM, 0);
}

// one block per (b, h): full causal attention over T=50, DH=128
__global__ void attn_kernel() {
    extern __shared__ float sm[];
    float* sQ = sm;                       // 50*128
    float* sK = sQ + TT * DH;             // 50*128
    float* sV = sK + TT * DH;             // 50*128
    float* sS = sV + TT * DH;             // 50*52

    int bh = blockIdx.x;
    int b = bh >> 3, h = bh & 7;
    int tid = threadIdx.x;                // 256 threads

    const float* Qb = g_Q + (long long)(b * TT) * HD + h * DH;
    const float* Kb = g_K + (long long)(b * TT) * HD + h * DH;
    const float* Vb = g_V + (long long)(b * TT) * HD + h * DH;

    for (int i = tid; i < TT * (DH / 4); i += 256) {
        int r = i >> 5, c = i & 31;  // 32 float4 per row
        ((float4*)sQ)[r * 32 + c] = *(const float4*)(Qb + (long long)r * HD + c * 4);
        ((float4*)sK)[r * 32 + c] = *(const float4*)(Kb + (long long)r * HD + c * 4);
        ((float4*)sV)[r * 32 + c] = *(const float4*)(Vb + (long long)r * HD + c * 4);
    }
    __syncthreads();

    const float scale = 0.08838834764831845f;  // 1/sqrt(128)
    for (int p = tid; p < TT * TT; p += 256) {
        int t = p / TT, s = p % TT;
        if (s > t) continue;                   // masked; never read
        const float4* q4 = (const float4*)(sQ + t * DH);
        const float4* k4 = (const float4*)(sK + s * DH);
        float acc = 0.0f;
#pragma unroll
        for (int kk = 0; kk < 32; kk++) {
            float4 a = q4[kk], bb = k4[kk];
            acc += a.x * bb.x + a.y * bb.y + a.z * bb.z + a.w * bb.w;
        }
        sS[t * 52 + s] = acc * scale;
    }
    __syncthreads();

    if (tid < TT) {
        int t = tid;
        float mx = -1e30f;
        for (int s = 0; s <= t; s++) mx = fmaxf(mx, sS[t * 52 + s]);
        float sum = 0.0f;
        for (int s = 0; s <= t; s++) { float e = expf(sS[t * 52 + s] - mx); sS[t * 52 + s] = e; sum += e; }
        float inv = 1.0f / sum;
        for (int s = 0; s <= t; s++) sS[t * 52 + s] *= inv;
    }
    __syncthreads();

    float* Ob = g_O + (long long)(b * TT) * HD + h * DH;
    int d = tid & 127;
    int th = tid >> 7;      // 0/1
    for (int i = 0; i < 25; i++) {
        int t = i * 2 + th;
        float acc = 0.0f;
        for (int s = 0; s <= t; s++) acc += sS[t * 52 + s] * sV[s * DH + d];
        Ob[(long long)t * HD + d] = acc;
    }
}

// a = g_O @ Wo + bo           grid (50, 1)
__global__ void proj_o_kernel(const float* __restrict__ Wo, const float* __restrict__ bo) {
    int m0 = blockIdx.x * 64;
    gemm64_core(g_O + (long long)m0 * HD, HD, Wo, EDIM, bo,
                g_a + (long long)m0 * EDIM, EDIM, HD, 0);
}
// m = gelu(a @ W1 + b1)       grid (50, 4)
__global__ void mlp1_kernel(const float* __restrict__ W1, const float* __restrict__ b1) {
    int m0 = blockIdx.x * 64;
    int n0 = blockIdx.y * 64;
    gemm64_core(g_a + (long long)m0 * EDIM, EDIM, W1 + n0, MDIM, b1 + n0,
                g_m + (long long)m0 * MDIM + n0, MDIM, EDIM, 1);
}
// y = m @ W2 + b2             grid (50, 1)
__global__ void mlp2_kernel(const float* __restrict__ W2, const float* __restrict__ b2) {
    int m0 = blockIdx.x * 64;
    gemm64_core(g_m + (long long)m0 * MDIM, MDIM, W2, EDIM, b2,
                g_y + (long long)m0 * EDIM, EDIM, MDIM, 0);
}
// logits = y @ Wf + bf        grid (50, 500)
__global__ void final_kernel(const float* __restrict__ Wf, const float* __restrict__ bf,
                             float* __restrict__ out) {
    int m0 = blockIdx.x * 64;
    int n0 = blockIdx.y * 64;
    gemm64_core(g_y + (long long)m0 * EDIM, EDIM, Wf + n0, VOC, bf + n0,
                out + (long long)m0 * VOC + n0, VOC, EDIM, 0);
}

// ---------------------------------------------------------------------------
extern "C" void kernel_launch(void* const* d_in, const int* in_sizes, int n_in,
                              void* d_out, int out_size) {
    (void)in_sizes; (void)n_in; (void)out_size;
    const int*   x   = (const int*)  d_in[0];
    const float* tok = (const float*)d_in[1];
    const float* pos = (const float*)d_in[2];
    const float* Wq  = (const float*)d_in[3];
    const float* bq  = (const float*)d_in[4];
    const float* Wk  = (const float*)d_in[5];
    const float* bk  = (const float*)d_in[6];
    const float* Wv  = (const float*)d_in[7];
    const float* bv  = (const float*)d_in[8];
    const float* Wo  = (const float*)d_in[9];
    const float* bo  = (const float*)d_in[10];
    const float* W1  = (const float*)d_in[11];
    const float* b1  = (const float*)d_in[12];
    const float* W2  = (const float*)d_in[13];
    const float* b2  = (const float*)d_in[14];
    const float* Wf  = (const float*)d_in[15];
    const float* bf  = (const float*)d_in[16];
    float* out = (float*)d_out;

    const int attn_smem = (3 * TT * DH + TT * 52) * (int)sizeof(float); // 87200 B
    cudaFuncSetAttribute(attn_kernel, cudaFuncAttributeMaxDynamicSharedMemorySize, attn_smem);

    embed_kernel<<<(NTOK * EDIM + 255) / 256, 256>>>(x, tok, pos);
    qkv_kernel<<<dim3(NTOK / 64, 2 * NH, 3), 256>>>(Wq, bq, Wk, bk, Wv, bv);
    attn_kernel<<<BATCH * NH, 256, attn_smem>>>();
    proj_o_kernel<<<dim3(NTOK / 64, 1), 256>>>(Wo, bo);
    mlp1_kernel<<<dim3(NTOK / 64, MDIM / 64), 256>>>(W1, b1);
    mlp2_kernel<<<dim3(NTOK / 64, 1), 256>>>(W2, b2);
    final_kernel<<<dim3(NTOK / 64, VOC / 64), 256>>>(Wf, bf, out);
}

// round 8
// speedup vs baseline: 1.2167x; 1.2167x over previous
#include <cuda_runtime.h>
#include <cuda_bf16.h>
#include <math.h>
#include <cstdint>

// Shapes
#define BATCH 64
#define TT    50
#define VOC   32000
#define EDIM  64
#define DH    128
#define NH    8
#define MDIM  256
#define NTOK  (BATCH*TT)      // 3200
#define HD    (NH*DH)         // 1024

// ---------------------------------------------------------------------------
// Scratch (no allocations allowed -> __device__ globals)
// ---------------------------------------------------------------------------
__device__ float g_h[NTOK*EDIM];
__device__ float g_Q[NTOK*HD];
__device__ float g_K[NTOK*HD];
__device__ float g_V[NTOK*HD];
__device__ float g_O[NTOK*HD];
__device__ float g_a[NTOK*EDIM];
__device__ float g_m[NTOK*MDIM];
__device__ float g_y[NTOK*EDIM];
__device__ float g_part[8*NTOK*EDIM];          // K-split partials
// Split-bf16 operands for the final vocab GEMM.
// A' row layout (per token): [hi(64) | hi(64) | lo(64)] bf16  -> 24 uint4
// B' row layout (per vocab): [hi(64) | lo(64) | hi(64)] bf16  -> 24 uint4
// Chunk products accumulate hi*hi + hi*lo + lo*hi (lo*lo ~2^-18, dropped).
__device__ uint4 g_ybf[NTOK*24];
__device__ uint4 g_Wfb[VOC*24];

// ---------------------------------------------------------------------------
// f32x2 packed math (FFMA2)
// ---------------------------------------------------------------------------
__device__ __forceinline__ unsigned long long pack2(float x, float y) {
    unsigned long long r;
    asm("mov.b64 %0, {%1, %2};" : "=l"(r) : "f"(x), "f"(y));
    return r;
}
__device__ __forceinline__ float2 unpack2(unsigned long long v) {
    float2 r;
    asm("mov.b64 {%0, %1}, %2;" : "=f"(r.x), "=f"(r.y) : "l"(v));
    return r;
}
__device__ __forceinline__ void ffma2(unsigned long long& d,
                                      unsigned long long a,
                                      unsigned long long b) {
    asm("fma.rn.f32x2 %0, %1, %2, %0;" : "+l"(d) : "l"(a), "l"(b));
}

__device__ __forceinline__ float act_apply(float v, int act) {
    if (act == 1) {
        v = 0.5f * v * (1.0f + erff(v * 0.70710678118654752f));
    }
    return v;
}

// ---------------------------------------------------------------------------
// Warp MMA (compute_80+; compiles at compute_103)
// ---------------------------------------------------------------------------
__device__ __forceinline__ void mma16816(float* d, const uint32_t* a, const uint32_t* b) {
    asm volatile("mma.sync.aligned.m16n8k16.row.col.f32.bf16.bf16.f32 "
        "{%0,%1,%2,%3}, {%4,%5,%6,%7}, {%8,%9}, {%0,%1,%2,%3};"
        : "+f"(d[0]), "+f"(d[1]), "+f"(d[2]), "+f"(d[3])
        : "r"(a[0]), "r"(a[1]), "r"(a[2]), "r"(a[3]), "r"(b[0]), "r"(b[1]));
}

// ---------------------------------------------------------------------------
// fp32x2 tile GEMM core: 64x64 tile, optional bias (nullptr -> 0), act.
// ---------------------------------------------------------------------------
__device__ void gemm64_core(const float* __restrict__ A, int lda,
                            const float* __restrict__ B, int ldb,
                            const float* __restrict__ bias,
                            float* __restrict__ C, int ldc,
                            int K, int act) {
    __shared__ float As[64][68];
    __shared__ float Bs[64][64];

    const int tid = threadIdx.x;
    const int tn  = (tid & 15) * 4;
    const int tm  = (tid >> 4) * 4;

    unsigned long long acc[4][2];
#pragma unroll
    for (int i = 0; i < 4; i++) { acc[i][0] = 0ull; acc[i][1] = 0ull; }

    for (int k0 = 0; k0 < K; k0 += 64) {
#pragma unroll
        for (int i = 0; i < 4; i++) {
            int idx = i * 256 + tid;
            int r = idx >> 4;
            int c = (idx & 15) * 4;
            float4 v = *(const float4*)(A + (long long)r * lda + k0 + c);
            *(float4*)&As[r][c] = v;
        }
#pragma unroll
        for (int i = 0; i < 4; i++) {
            int idx = i * 256 + tid;
            int r = idx >> 4;
            int c = (idx & 15) * 4;
            float4 v = *(const float4*)(B + (long long)(k0 + r) * ldb + c);
            *(float4*)&Bs[r][c] = v;
        }
        __syncthreads();

#pragma unroll 8
        for (int k = 0; k < 64; k++) {
            float a0 = As[tm + 0][k];
            float a1 = As[tm + 1][k];
            float a2 = As[tm + 2][k];
            float a3 = As[tm + 3][k];
            float4 b4 = *(const float4*)&Bs[k][tn];
            unsigned long long b01 = pack2(b4.x, b4.y);
            unsigned long long b23 = pack2(b4.z, b4.w);
            unsigned long long aa;
            aa = pack2(a0, a0); ffma2(acc[0][0], aa, b01); ffma2(acc[0][1], aa, b23);
            aa = pack2(a1, a1); ffma2(acc[1][0], aa, b01); ffma2(acc[1][1], aa, b23);
            aa = pack2(a2, a2); ffma2(acc[2][0], aa, b01); ffma2(acc[2][1], aa, b23);
            aa = pack2(a3, a3); ffma2(acc[3][0], aa, b01); ffma2(acc[3][1], aa, b23);
        }
        __syncthreads();
    }

    float4 bv4 = make_float4(0.f, 0.f, 0.f, 0.f);
    if (bias) bv4 = *(const float4*)(bias + tn);
#pragma unroll
    for (int i = 0; i < 4; i++) {
        float2 p0 = unpack2(acc[i][0]);
        float2 p1 = unpack2(acc[i][1]);
        float4 o;
        o.x = act_apply(p0.x + bv4.x, act);
        o.y = act_apply(p0.y + bv4.y, act);
        o.z = act_apply(p1.x + bv4.z, act);
        o.w = act_apply(p1.y + bv4.w, act);
        *(float4*)(C + (long long)(tm + i) * ldc + tn) = o;
    }
}

// ---------------------------------------------------------------------------
// Kernels
// ---------------------------------------------------------------------------
__global__ void embed_kernel(const int* __restrict__ x,
                             const float* __restrict__ tok,
                             const float* __restrict__ pos) {
    int i = blockIdx.x * 256 + threadIdx.x;
    if (i >= NTOK * EDIM) return;
    int m = i >> 6;
    int e = i & 63;
    int t = m % TT;
    int id = x[m];
    g_h[i] = tok[id * EDIM + e] + pos[t * EDIM + e];
}

__global__ void qkv_kernel(const float* __restrict__ Wq, const float* __restrict__ bq,
                           const float* __restrict__ Wk, const float* __restrict__ bk,
                           const float* __restrict__ Wv, const float* __restrict__ bv) {
    int m0   = blockIdx.x * 64;
    int head = blockIdx.y >> 1;
    int dt   = blockIdx.y & 1;
    const float* W; const float* bb; float* C;
    if (blockIdx.z == 0)      { W = Wq; bb = bq; C = g_Q; }
    else if (blockIdx.z == 1) { W = Wk; bb = bk; C = g_K; }
    else                      { W = Wv; bb = bv; C = g_V; }
    int n0 = head * DH + dt * 64;
    gemm64_core(g_h + (long long)m0 * EDIM, EDIM,
                W + head * EDIM * DH + dt * 64, DH,
                bb + n0,
                C + (long long)m0 * HD + n0, HD,
                EDIM, 0);
}

__global__ void attn_kernel() {
    extern __shared__ float sm[];
    float* sQ = sm;
    float* sK = sQ + TT * DH;
    float* sV = sK + TT * DH;
    float* sS = sV + TT * DH;

    int bh = blockIdx.x;
    int b = bh >> 3, h = bh & 7;
    int tid = threadIdx.x;

    const float* Qb = g_Q + (long long)(b * TT) * HD + h * DH;
    const float* Kb = g_K + (long long)(b * TT) * HD + h * DH;
    const float* Vb = g_V + (long long)(b * TT) * HD + h * DH;

    for (int i = tid; i < TT * (DH / 4); i += 256) {
        int r = i >> 5, c = i & 31;
        ((float4*)sQ)[r * 32 + c] = *(const float4*)(Qb + (long long)r * HD + c * 4);
        ((float4*)sK)[r * 32 + c] = *(const float4*)(Kb + (long long)r * HD + c * 4);
        ((float4*)sV)[r * 32 + c] = *(const float4*)(Vb + (long long)r * HD + c * 4);
    }
    __syncthreads();

    const float scale = 0.08838834764831845f;
    for (int p = tid; p < TT * TT; p += 256) {
        int t = p / TT, s = p % TT;
        if (s > t) continue;
        const float4* q4 = (const float4*)(sQ + t * DH);
        const float4* k4 = (const float4*)(sK + s * DH);
        float acc = 0.0f;
#pragma unroll
        for (int kk = 0; kk < 32; kk++) {
            float4 a = q4[kk], bb = k4[kk];
            acc += a.x * bb.x + a.y * bb.y + a.z * bb.z + a.w * bb.w;
        }
        sS[t * 52 + s] = acc * scale;
    }
    __syncthreads();

    if (tid < TT) {
        int t = tid;
        float mx = -1e30f;
        for (int s = 0; s <= t; s++) mx = fmaxf(mx, sS[t * 52 + s]);
        float sum = 0.0f;
        for (int s = 0; s <= t; s++) { float e = expf(sS[t * 52 + s] - mx); sS[t * 52 + s] = e; sum += e; }
        float inv = 1.0f / sum;
        for (int s = 0; s <= t; s++) sS[t * 52 + s] *= inv;
    }
    __syncthreads();

    float* Ob = g_O + (long long)(b * TT) * HD + h * DH;
    int d = tid & 127;
    int th = tid >> 7;
    for (int i = 0; i < 25; i++) {
        int t = i * 2 + th;
        float acc = 0.0f;
        for (int s = 0; s <= t; s++) acc += sS[t * 52 + s] * sV[s * DH + d];
        Ob[(long long)t * HD + d] = acc;
    }
}

// a-partials: K split 8x128.   grid (50, 8)
__global__ void proj_o_part_kernel(const float* __restrict__ Wo) {
    int m0 = blockIdx.x * 64;
    int ks = blockIdx.y;
    gemm64_core(g_O + (long long)m0 * HD + ks * 128, HD,
                Wo + (long long)ks * 128 * EDIM, EDIM, nullptr,
                g_part + (long long)ks * NTOK * EDIM + (long long)m0 * EDIM, EDIM,
                128, 0);
}
// y-partials: K split 4x64.    grid (50, 4)
__global__ void mlp2_part_kernel(const float* __restrict__ W2) {
    int m0 = blockIdx.x * 64;
    int ks = blockIdx.y;
    gemm64_core(g_m + (long long)m0 * MDIM + ks * 64, MDIM,
                W2 + (long long)ks * 64 * EDIM, EDIM, nullptr,
                g_part + (long long)ks * NTOK * EDIM + (long long)m0 * EDIM, EDIM,
                64, 0);
}
// Deterministic partial reduce + bias.
// DST selects the destination GLOBAL in device code (a __device__ symbol must
// never be passed as a kernel argument from host code - that was the R6/R7
// failure: host shadow address -> illegal device write -> poisoned context).
template <int NSPLIT, int DST>   // DST: 0 -> g_a, 1 -> g_y
__global__ void reduce_part_kernel(const float* __restrict__ bias) {
    float* dst = (DST == 0) ? g_a : g_y;
    int i = blockIdx.x * 256 + threadIdx.x;
    if (i >= NTOK * EDIM) return;
    float s = bias[i & 63];
#pragma unroll
    for (int k = 0; k < NSPLIT; k++) s += g_part[(long long)k * NTOK * EDIM + i];
    dst[i] = s;
}

// m = gelu(a @ W1 + b1)       grid (50, 4)
__global__ void mlp1_kernel(const float* __restrict__ W1, const float* __restrict__ b1) {
    int m0 = blockIdx.x * 64;
    int n0 = blockIdx.y * 64;
    gemm64_core(g_a + (long long)m0 * EDIM, EDIM, W1 + n0, MDIM, b1 + n0,
                g_m + (long long)m0 * MDIM + n0, MDIM, EDIM, 1);
}

// ---------------------------------------------------------------------------
// Split-bf16 operand prep for final GEMM
// ---------------------------------------------------------------------------
__device__ __forceinline__ void split_bf16(float v, unsigned short& hi, unsigned short& lo) {
    __nv_bfloat16 h = __float2bfloat16(v);
    float r = v - __bfloat162float(h);
    __nv_bfloat16 l = __float2bfloat16(r);
    hi = *reinterpret_cast<unsigned short*>(&h);
    lo = *reinterpret_cast<unsigned short*>(&l);
}

// A' = [hi | hi | lo] per token row.  1 thread per output u32 (96 per row).
__global__ void split_y_kernel() {
    int i = blockIdx.x * 256 + threadIdx.x;
    if (i >= NTOK * 96) return;
    int r = i / 96, j = i % 96;
    int jj = (j < 32) ? j : (j < 64 ? j - 32 : j - 64);
    bool lo_plane = (j >= 64);
    float v0 = g_y[r * 64 + 2 * jj];
    float v1 = g_y[r * 64 + 2 * jj + 1];
    unsigned short h0, l0, h1, l1;
    split_bf16(v0, h0, l0);
    split_bf16(v1, h1, l1);
    unsigned int w = lo_plane ? ((unsigned int)l0 | ((unsigned int)l1 << 16))
                              : ((unsigned int)h0 | ((unsigned int)h1 << 16));
    ((unsigned int*)g_ybf)[r * 96 + j] = w;
}

// B' = [hi | lo | hi] per vocab row. Wf is [E][V] -> transpose via smem tile.
__global__ void split_wf_kernel(const float* __restrict__ Wf) {
    __shared__ unsigned short sH[128][68];
    __shared__ unsigned short sL[128][68];
    int n0 = blockIdx.x * 128;
    int tid = threadIdx.x;  // 128
    for (int i = tid; i < 64 * 128; i += 128) {
        int e = i >> 7;
        int n = i & 127;
        float v = Wf[(long long)e * VOC + n0 + n];
        unsigned short h, l;
        split_bf16(v, h, l);
        sH[n][e] = h;
        sL[n][e] = l;
    }
    __syncthreads();
    for (int i = tid; i < 128 * 96; i += 128) {
        int n = i / 96, j = i % 96;
        unsigned int w;
        if (j < 32)       w = (unsigned int)sH[n][2*j]        | ((unsigned int)sH[n][2*j+1] << 16);
        else if (j < 64)  w = (unsigned int)sL[n][2*(j-32)]   | ((unsigned int)sL[n][2*(j-32)+1] << 16);
        else              w = (unsigned int)sH[n][2*(j-64)]   | ((unsigned int)sH[n][2*(j-64)+1] << 16);
        ((unsigned int*)g_Wfb)[(long long)(n0 + n) * 96 + j] = w;
    }
}

// ---------------------------------------------------------------------------
// Final vocab GEMM on mma.sync m16n8k16 bf16, direct-lds fragments.
// Block tile 128x128, 8 warps (4m x 2n), warp tile 32x64.
// K=192 processed as 3 chunks of 64 (smem reload per chunk; acc persists).
// Smem: 512 (bias) + 2 * 128 rows * 72 elems * 2B = 37376 B < 48KB default.
// ---------------------------------------------------------------------------
#define FC_LDS   72                         // 64 + 8 pad bf16 per smem row

__global__ __launch_bounds__(256) void final_mma_kernel(
        const float* __restrict__ bf, float* __restrict__ out) {
    __shared__ float sBias[128];
    __shared__ __align__(16) __nv_bfloat16 sA[128 * FC_LDS];
    __shared__ __align__(16) __nv_bfloat16 sB[128 * FC_LDS];

    const int tid = threadIdx.x;
    const int m0 = blockIdx.x * 128;
    const int n0 = blockIdx.y * 128;

    if (tid < 128) sBias[tid] = bf[n0 + tid];

    const uint4* __restrict__ Ag = g_ybf + (long long)m0 * 24;
    const uint4* __restrict__ Bg = g_Wfb + (long long)n0 * 24;

    const int wid  = tid >> 5, lane = tid & 31;
    const int wm   = wid >> 1;            // 0..3  (m strip of 32)
    const int wn   = wid & 1;             // 0..1  (n strip of 64)
    const int l4   = lane >> 2;           // 0..7  groupID
    const int lm   = lane & 3;            // 0..3  threadID_in_group

    float acc[2][8][4];
#pragma unroll
    for (int mf = 0; mf < 2; mf++)
#pragma unroll
        for (int nf = 0; nf < 8; nf++)
#pragma unroll
            for (int c = 0; c < 4; c++) acc[mf][nf][c] = 0.0f;

#pragma unroll
    for (int ch = 0; ch < 3; ch++) {
        // Load chunk ch: uint4 columns [ch*8, ch*8+8) of each 128-row tile.
#pragma unroll
        for (int i = 0; i < 4; i++) {
            int idx = i * 256 + tid;          // 0..1023
            int r = idx >> 3, q = idx & 7;
            *(uint4*)(sA + r * FC_LDS + q * 8) = Ag[(long long)r * 24 + ch * 8 + q];
            *(uint4*)(sB + r * FC_LDS + q * 8) = Bg[(long long)r * 24 + ch * 8 + q];
        }
        __syncthreads();

#pragma unroll
        for (int ks = 0; ks < 4; ks++) {
            const int k0 = ks * 16;
            // A fragments: two 16x16 blocks (mf), rows wm*32 + mf*16 + ...
            uint32_t a[2][4];
#pragma unroll
            for (int mf = 0; mf < 2; mf++) {
                const __nv_bfloat16* base = sA + (wm * 32 + mf * 16 + l4) * FC_LDS + k0 + lm * 2;
                a[mf][0] = *(const uint32_t*)(base);
                a[mf][1] = *(const uint32_t*)(base + 8 * FC_LDS);
                a[mf][2] = *(const uint32_t*)(base + 8);
                a[mf][3] = *(const uint32_t*)(base + 8 * FC_LDS + 8);
            }
            // B fragments: 8 k16 x n8 blocks
            uint32_t b[8][2];
#pragma unroll
            for (int nf = 0; nf < 8; nf++) {
                const __nv_bfloat16* base = sB + (wn * 64 + nf * 8 + l4) * FC_LDS + k0 + lm * 2;
                b[nf][0] = *(const uint32_t*)(base);
                b[nf][1] = *(const uint32_t*)(base + 8);
            }
#pragma unroll
            for (int mf = 0; mf < 2; mf++)
#pragma unroll
                for (int nf = 0; nf < 8; nf++)
                    mma16816(acc[mf][nf], a[mf], b[nf]);
        }
        __syncthreads();
    }

    // Epilogue: add bias, store fp32.
#pragma unroll
    for (int mf = 0; mf < 2; mf++) {
        int row = m0 + wm * 32 + mf * 16 + l4;
        float* o0 = out + (long long)row * VOC + n0;
        float* o1 = out + (long long)(row + 8) * VOC + n0;
#pragma unroll
        for (int nf = 0; nf < 8; nf++) {
            int colr = wn * 64 + nf * 8 + lm * 2;
            float bx = sBias[colr], by = sBias[colr + 1];
            float2 v0 = make_float2(acc[mf][nf][0] + bx, acc[mf][nf][1] + by);
            float2 v1 = make_float2(acc[mf][nf][2] + bx, acc[mf][nf][3] + by);
            *(float2*)(o0 + colr) = v0;
            *(float2*)(o1 + colr) = v1;
        }
    }
}

// ---------------------------------------------------------------------------
extern "C" void kernel_launch(void* const* d_in, const int* in_sizes, int n_in,
                              void* d_out, int out_size) {
    (void)in_sizes; (void)n_in; (void)out_size;
    const int*   x   = (const int*)  d_in[0];
    const float* tok = (const float*)d_in[1];
    const float* pos = (const float*)d_in[2];
    const float* Wq  = (const float*)d_in[3];
    const float* bq  = (const float*)d_in[4];
    const float* Wk  = (const float*)d_in[5];
    const float* bk  = (const float*)d_in[6];
    const float* Wv  = (const float*)d_in[7];
    const float* bv  = (const float*)d_in[8];
    const float* Wo  = (const float*)d_in[9];
    const float* bo  = (const float*)d_in[10];
    const float* W1  = (const float*)d_in[11];
    const float* b1  = (const float*)d_in[12];
    const float* W2  = (const float*)d_in[13];
    const float* b2  = (const float*)d_in[14];
    const float* Wf  = (const float*)d_in[15];
    const float* bf  = (const float*)d_in[16];
    float* out = (float*)d_out;

    const int attn_smem = (3 * TT * DH + TT * 52) * (int)sizeof(float);
    cudaFuncSetAttribute(attn_kernel, cudaFuncAttributeMaxDynamicSharedMemorySize, attn_smem);

    // Wf split is independent of everything else — kick it off first.
    split_wf_kernel<<<VOC / 128, 128>>>(Wf);

    embed_kernel<<<(NTOK * EDIM + 255) / 256, 256>>>(x, tok, pos);
    qkv_kernel<<<dim3(NTOK / 64, 2 * NH, 3), 256>>>(Wq, bq, Wk, bk, Wv, bv);
    attn_kernel<<<BATCH * NH, 256, attn_smem>>>();

    proj_o_part_kernel<<<dim3(NTOK / 64, 8), 256>>>(Wo);
    reduce_part_kernel<8, 0><<<(NTOK * EDIM + 255) / 256, 256>>>(bo);

    mlp1_kernel<<<dim3(NTOK / 64, MDIM / 64), 256>>>(W1, b1);

    mlp2_part_kernel<<<dim3(NTOK / 64, 4), 256>>>(W2);
    reduce_part_kernel<4, 1><<<(NTOK * EDIM + 255) / 256, 256>>>(b2);

    split_y_kernel<<<(NTOK * 96 + 255) / 256, 256>>>();

    final_mma_kernel<<<dim3(NTOK / 128, VOC / 128), 256>>>(bf, out);
}

// round 9
// speedup vs baseline: 1.4709x; 1.2089x over previous
#include <cuda_runtime.h>
#include <cuda_bf16.h>
#include <math.h>
#include <cstdint>

// Shapes
#define BATCH 64
#define TT    50
#define VOC   32000
#define EDIM  64
#define DH    128
#define NH    8
#define MDIM  256
#define NTOK  (BATCH*TT)      // 3200
#define HD    (NH*DH)         // 1024

// ---------------------------------------------------------------------------
// Scratch (no allocations allowed -> __device__ globals)
// ---------------------------------------------------------------------------
__device__ float g_h[NTOK*EDIM];
__device__ float g_Q[NTOK*HD];
__device__ float g_K[NTOK*HD];
__device__ float g_V[NTOK*HD];
__device__ float g_O[NTOK*HD];
__device__ float g_a[NTOK*EDIM];
__device__ float g_m[NTOK*MDIM];
__device__ float g_y[NTOK*EDIM];
__device__ float g_part[8*NTOK*EDIM];          // K-split partials
// Split-bf16 operands for the final vocab GEMM.
// A' row layout (per token): [hi(64) | hi(64) | lo(64)] bf16  -> 24 uint4
// B' row layout (per vocab): [hi(64) | lo(64) | hi(64)] bf16  -> 24 uint4
// Chunk products accumulate hi*hi + hi*lo + lo*hi (lo*lo ~2^-18, dropped).
__device__ uint4 g_ybf[NTOK*24];
__device__ uint4 g_Wfb[VOC*24];

// ---------------------------------------------------------------------------
// f32x2 packed math (FFMA2)
// ---------------------------------------------------------------------------
__device__ __forceinline__ unsigned long long pack2(float x, float y) {
    unsigned long long r;
    asm("mov.b64 %0, {%1, %2};" : "=l"(r) : "f"(x), "f"(y));
    return r;
}
__device__ __forceinline__ float2 unpack2(unsigned long long v) {
    float2 r;
    asm("mov.b64 {%0, %1}, %2;" : "=f"(r.x), "=f"(r.y) : "l"(v));
    return r;
}
__device__ __forceinline__ void ffma2(unsigned long long& d,
                                      unsigned long long a,
                                      unsigned long long b) {
    asm("fma.rn.f32x2 %0, %1, %2, %0;" : "+l"(d) : "l"(a), "l"(b));
}

__device__ __forceinline__ float act_apply(float v, int act) {
    if (act == 1) {
        v = 0.5f * v * (1.0f + erff(v * 0.70710678118654752f));
    }
    return v;
}

// ---------------------------------------------------------------------------
// Warp MMA (compute_80+; compiles at compute_103)
// ---------------------------------------------------------------------------
__device__ __forceinline__ void mma16816(float* d, const uint32_t* a, const uint32_t* b) {
    asm volatile("mma.sync.aligned.m16n8k16.row.col.f32.bf16.bf16.f32 "
        "{%0,%1,%2,%3}, {%4,%5,%6,%7}, {%8,%9}, {%0,%1,%2,%3};"
        : "+f"(d[0]), "+f"(d[1]), "+f"(d[2]), "+f"(d[3])
        : "r"(a[0]), "r"(a[1]), "r"(a[2]), "r"(a[3]), "r"(b[0]), "r"(b[1]));
}

// ---------------------------------------------------------------------------
// fp32x2 tile GEMM core: 64x64 tile, optional bias (nullptr -> 0), act.
// ---------------------------------------------------------------------------
__device__ void gemm64_core(const float* __restrict__ A, int lda,
                            const float* __restrict__ B, int ldb,
                            const float* __restrict__ bias,
                            float* __restrict__ C, int ldc,
                            int K, int act) {
    __shared__ float As[64][68];
    __shared__ float Bs[64][64];

    const int tid = threadIdx.x;
    const int tn  = (tid & 15) * 4;
    const int tm  = (tid >> 4) * 4;

    unsigned long long acc[4][2];
#pragma unroll
    for (int i = 0; i < 4; i++) { acc[i][0] = 0ull; acc[i][1] = 0ull; }

    for (int k0 = 0; k0 < K; k0 += 64) {
#pragma unroll
        for (int i = 0; i < 4; i++) {
            int idx = i * 256 + tid;
            int r = idx >> 4;
            int c = (idx & 15) * 4;
            float4 v = *(const float4*)(A + (long long)r * lda + k0 + c);
            *(float4*)&As[r][c] = v;
        }
#pragma unroll
        for (int i = 0; i < 4; i++) {
            int idx = i * 256 + tid;
            int r = idx >> 4;
            int c = (idx & 15) * 4;
            float4 v = *(const float4*)(B + (long long)(k0 + r) * ldb + c);
            *(float4*)&Bs[r][c] = v;
        }
        __syncthreads();

#pragma unroll 8
        for (int k = 0; k < 64; k++) {
            float a0 = As[tm + 0][k];
            float a1 = As[tm + 1][k];
            float a2 = As[tm + 2][k];
            float a3 = As[tm + 3][k];
            float4 b4 = *(const float4*)&Bs[k][tn];
            unsigned long long b01 = pack2(b4.x, b4.y);
            unsigned long long b23 = pack2(b4.z, b4.w);
            unsigned long long aa;
            aa = pack2(a0, a0); ffma2(acc[0][0], aa, b01); ffma2(acc[0][1], aa, b23);
            aa = pack2(a1, a1); ffma2(acc[1][0], aa, b01); ffma2(acc[1][1], aa, b23);
            aa = pack2(a2, a2); ffma2(acc[2][0], aa, b01); ffma2(acc[2][1], aa, b23);
            aa = pack2(a3, a3); ffma2(acc[3][0], aa, b01); ffma2(acc[3][1], aa, b23);
        }
        __syncthreads();
    }

    float4 bv4 = make_float4(0.f, 0.f, 0.f, 0.f);
    if (bias) bv4 = *(const float4*)(bias + tn);
#pragma unroll
    for (int i = 0; i < 4; i++) {
        float2 p0 = unpack2(acc[i][0]);
        float2 p1 = unpack2(acc[i][1]);
        float4 o;
        o.x = act_apply(p0.x + bv4.x, act);
        o.y = act_apply(p0.y + bv4.y, act);
        o.z = act_apply(p1.x + bv4.z, act);
        o.w = act_apply(p1.y + bv4.w, act);
        *(float4*)(C + (long long)(tm + i) * ldc + tn) = o;
    }
}

// ---------------------------------------------------------------------------
// Kernels
// ---------------------------------------------------------------------------
__global__ void embed_kernel(const int* __restrict__ x,
                             const float* __restrict__ tok,
                             const float* __restrict__ pos) {
    int i = blockIdx.x * 256 + threadIdx.x;
    if (i >= NTOK * EDIM) return;
    int m = i >> 6;
    int e = i & 63;
    int t = m % TT;
    int id = x[m];
    g_h[i] = tok[id * EDIM + e] + pos[t * EDIM + e];
}

__global__ void qkv_kernel(const float* __restrict__ Wq, const float* __restrict__ bq,
                           const float* __restrict__ Wk, const float* __restrict__ bk,
                           const float* __restrict__ Wv, const float* __restrict__ bv) {
    int m0   = blockIdx.x * 64;
    int head = blockIdx.y >> 1;
    int dt   = blockIdx.y & 1;
    const float* W; const float* bb; float* C;
    if (blockIdx.z == 0)      { W = Wq; bb = bq; C = g_Q; }
    else if (blockIdx.z == 1) { W = Wk; bb = bk; C = g_K; }
    else                      { W = Wv; bb = bv; C = g_V; }
    int n0 = head * DH + dt * 64;
    gemm64_core(g_h + (long long)m0 * EDIM, EDIM,
                W + head * EDIM * DH + dt * 64, DH,
                bb + n0,
                C + (long long)m0 * HD + n0, HD,
                EDIM, 0);
}

// ---------------------------------------------------------------------------
// Attention: one block per (b,h). Register-tiled micro-GEMMs.
// Smem layout (floats):
//   sQT [128][64]  k-major Q^T   (cols t, zero-padded t>=50)
//   sKT [128][64]  k-major K^T
//   sV  [50][128]  s-major V
//   sS  [64][68]   scores -> probabilities (t-major, padded)
// Total 27136 floats = 108544 B -> 2 CTAs/SM.
// ---------------------------------------------------------------------------
#define AT_QT 0
#define AT_KT 8192
#define AT_V  16384
#define AT_S  22784
#define AT_SMEM (27136 * 4)

__global__ __launch_bounds__(256) void attn_kernel() {
    extern __shared__ float sm[];
    float* sQT = sm + AT_QT;
    float* sKT = sm + AT_KT;
    float* sV  = sm + AT_V;
    float* sS  = sm + AT_S;

    int bh = blockIdx.x;
    int b = bh >> 3, h = bh & 7;
    int tid = threadIdx.x;

    const float* Qb = g_Q + (long long)(b * TT) * HD + h * DH;
    const float* Kb = g_K + (long long)(b * TT) * HD + h * DH;
    const float* Vb = g_V + (long long)(b * TT) * HD + h * DH;

    // Load Q,K transposed into [k][t] layout; zero-pad t in [50,64).
    for (int i = tid; i < 2048; i += 256) {      // 32 d4-groups x 64 t
        int d4 = i >> 6, t = i & 63;
        float4 q = make_float4(0.f, 0.f, 0.f, 0.f);
        float4 k = make_float4(0.f, 0.f, 0.f, 0.f);
        if (t < TT) {
            q = *(const float4*)(Qb + (long long)t * HD + d4 * 4);
            k = *(const float4*)(Kb + (long long)t * HD + d4 * 4);
        }
        int r = d4 * 4;
        sQT[(r + 0) * 64 + t] = q.x;
        sQT[(r + 1) * 64 + t] = q.y;
        sQT[(r + 2) * 64 + t] = q.z;
        sQT[(r + 3) * 64 + t] = q.w;
        sKT[(r + 0) * 64 + t] = k.x;
        sKT[(r + 1) * 64 + t] = k.y;
        sKT[(r + 2) * 64 + t] = k.z;
        sKT[(r + 3) * 64 + t] = k.w;
    }
    // Load V rows [50][128] directly.
    for (int i = tid; i < TT * 32; i += 256) {
        int s = i >> 5, c = i & 31;
        *(float4*)&sV[s * 128 + c * 4] = *(const float4*)(Vb + (long long)s * HD + c * 4);
    }
    __syncthreads();

    // ---- Phase A: scores S[t][s] = Q[t]·K[s], 64x64 tile, 4x4 micro ----
    {
        const int tn = (tid & 15) * 4;   // s
        const int tm = (tid >> 4) * 4;   // t
        unsigned long long acc[4][2];
#pragma unroll
        for (int i = 0; i < 4; i++) { acc[i][0] = 0ull; acc[i][1] = 0ull; }

#pragma unroll 4
        for (int k = 0; k < 128; k++) {
            float4 q4 = *(const float4*)&sQT[k * 64 + tm];
            float4 k4 = *(const float4*)&sKT[k * 64 + tn];
            unsigned long long b01 = pack2(k4.x, k4.y);
            unsigned long long b23 = pack2(k4.z, k4.w);
            unsigned long long aa;
            aa = pack2(q4.x, q4.x); ffma2(acc[0][0], aa, b01); ffma2(acc[0][1], aa, b23);
            aa = pack2(q4.y, q4.y); ffma2(acc[1][0], aa, b01); ffma2(acc[1][1], aa, b23);
            aa = pack2(q4.z, q4.z); ffma2(acc[2][0], aa, b01); ffma2(acc[2][1], aa, b23);
            aa = pack2(q4.w, q4.w); ffma2(acc[3][0], aa, b01); ffma2(acc[3][1], aa, b23);
        }
        const float scale = 0.08838834764831845f;  // 1/sqrt(128)
#pragma unroll
        for (int i = 0; i < 4; i++) {
            float2 p0 = unpack2(acc[i][0]);
            float2 p1 = unpack2(acc[i][1]);
            float4 o = make_float4(p0.x * scale, p0.y * scale, p1.x * scale, p1.y * scale);
            *(float4*)&sS[(tm + i) * 68 + tn] = o;
        }
    }
    __syncthreads();

    // ---- Softmax per row t (causal), zero masked region s in (t,50) ----
    if (tid < TT) {
        int t = tid;
        float* row = sS + t * 68;
        float mx = -1e30f;
        for (int s = 0; s <= t; s++) mx = fmaxf(mx, row[s]);
        float sum = 0.0f;
        for (int s = 0; s <= t; s++) { float e = expf(row[s] - mx); row[s] = e; sum += e; }
        float inv = 1.0f / sum;
        for (int s = 0; s <= t; s++) row[s] *= inv;
        for (int s = t + 1; s < TT; s++) row[s] = 0.0f;
    }
    __syncthreads();

    // ---- Phase B: O[t][d] = sum_s P[t][s] * V[s][d], 8x4 micro ----
    {
        const int tm = (tid >> 5) * 8;   // t  (8 groups x 8 = 64)
        const int tn = (tid & 31) * 4;   // d  (32 groups x 4 = 128)
        unsigned long long acc[8][2];
#pragma unroll
        for (int i = 0; i < 8; i++) { acc[i][0] = 0ull; acc[i][1] = 0ull; }

#pragma unroll 2
        for (int s = 0; s < TT; s++) {
            float4 v4 = *(const float4*)&sV[s * 128 + tn];
            unsigned long long b01 = pack2(v4.x, v4.y);
            unsigned long long b23 = pack2(v4.z, v4.w);
#pragma unroll
            for (int i = 0; i < 8; i++) {
                float p = sS[(tm + i) * 68 + s];      // warp-broadcast
                unsigned long long aa = pack2(p, p);
                ffma2(acc[i][0], aa, b01);
                ffma2(acc[i][1], aa, b23);
            }
        }

        float* Ob = g_O + (long long)(b * TT) * HD + h * DH;
#pragma unroll
        for (int i = 0; i < 8; i++) {
            int t = tm + i;
            if (t < TT) {
                float2 p0 = unpack2(acc[i][0]);
                float2 p1 = unpack2(acc[i][1]);
                float4 o = make_float4(p0.x, p0.y, p1.x, p1.y);
                *(float4*)(Ob + (long long)t * HD + tn) = o;
            }
        }
    }
}

// a-partials: K split 8x128.   grid (50, 8)
__global__ void proj_o_part_kernel(const float* __restrict__ Wo) {
    int m0 = blockIdx.x * 64;
    int ks = blockIdx.y;
    gemm64_core(g_O + (long long)m0 * HD + ks * 128, HD,
                Wo + (long long)ks * 128 * EDIM, EDIM, nullptr,
                g_part + (long long)ks * NTOK * EDIM + (long long)m0 * EDIM, EDIM,
                128, 0);
}
// y-partials: K split 4x64.    grid (50, 4)
__global__ void mlp2_part_kernel(const float* __restrict__ W2) {
    int m0 = blockIdx.x * 64;
    int ks = blockIdx.y;
    gemm64_core(g_m + (long long)m0 * MDIM + ks * 64, MDIM,
                W2 + (long long)ks * 64 * EDIM, EDIM, nullptr,
                g_part + (long long)ks * NTOK * EDIM + (long long)m0 * EDIM, EDIM,
                64, 0);
}
// Deterministic partial reduce + bias. DST selects the destination global in
// device code (never pass a __device__ symbol as a kernel arg from host).
template <int NSPLIT, int DST>   // DST: 0 -> g_a, 1 -> g_y
__global__ void reduce_part_kernel(const float* __restrict__ bias) {
    float* dst = (DST == 0) ? g_a : g_y;
    int i = blockIdx.x * 256 + threadIdx.x;
    if (i >= NTOK * EDIM) return;
    float s = bias[i & 63];
#pragma unroll
    for (int k = 0; k < NSPLIT; k++) s += g_part[(long long)k * NTOK * EDIM + i];
    dst[i] = s;
}

// m = gelu(a @ W1 + b1)       grid (50, 4)
__global__ void mlp1_kernel(const float* __restrict__ W1, const float* __restrict__ b1) {
    int m0 = blockIdx.x * 64;
    int n0 = blockIdx.y * 64;
    gemm64_core(g_a + (long long)m0 * EDIM, EDIM, W1 + n0, MDIM, b1 + n0,
                g_m + (long long)m0 * MDIM + n0, MDIM, EDIM, 1);
}

// ---------------------------------------------------------------------------
// Split-bf16 operand prep for final GEMM
// ---------------------------------------------------------------------------
__device__ __forceinline__ void split_bf16(float v, unsigned short& hi, unsigned short& lo) {
    __nv_bfloat16 h = __float2bfloat16(v);
    float r = v - __bfloat162float(h);
    __nv_bfloat16 l = __float2bfloat16(r);
    hi = *reinterpret_cast<unsigned short*>(&h);
    lo = *reinterpret_cast<unsigned short*>(&l);
}

// A' = [hi | hi | lo] per token row.  1 thread per output u32 (96 per row).
__global__ void split_y_kernel() {
    int i = blockIdx.x * 256 + threadIdx.x;
    if (i >= NTOK * 96) return;
    int r = i / 96, j = i % 96;
    int jj = (j < 32) ? j : (j < 64 ? j - 32 : j - 64);
    bool lo_plane = (j >= 64);
    float v0 = g_y[r * 64 + 2 * jj];
    float v1 = g_y[r * 64 + 2 * jj + 1];
    unsigned short h0, l0, h1, l1;
    split_bf16(v0, h0, l0);
    split_bf16(v1, h1, l1);
    unsigned int w = lo_plane ? ((unsigned int)l0 | ((unsigned int)l1 << 16))
                              : ((unsigned int)h0 | ((unsigned int)h1 << 16));
    ((unsigned int*)g_ybf)[r * 96 + j] = w;
}

// B' = [hi | lo | hi] per vocab row. Wf is [E][V] -> transpose via smem tile.
__global__ void split_wf_kernel(const float* __restrict__ Wf) {
    __shared__ unsigned short sH[128][68];
    __shared__ unsigned short sL[128][68];
    int n0 = blockIdx.x * 128;
    int tid = threadIdx.x;  // 128
    for (int i = tid; i < 64 * 128; i += 128) {
        int e = i >> 7;
        int n = i & 127;
        float v = Wf[(long long)e * VOC + n0 + n];
        unsigned short h, l;
        split_bf16(v, h, l);
        sH[n][e] = h;
        sL[n][e] = l;
    }
    __syncthreads();
    for (int i = tid; i < 128 * 96; i += 128) {
        int n = i / 96, j = i % 96;
        unsigned int w;
        if (j < 32)       w = (unsigned int)sH[n][2*j]        | ((unsigned int)sH[n][2*j+1] << 16);
        else if (j < 64)  w = (unsigned int)sL[n][2*(j-32)]   | ((unsigned int)sL[n][2*(j-32)+1] << 16);
        else              w = (unsigned int)sH[n][2*(j-64)]   | ((unsigned int)sH[n][2*(j-64)+1] << 16);
        ((unsigned int*)g_Wfb)[(long long)(n0 + n) * 96 + j] = w;
    }
}

// ---------------------------------------------------------------------------
// Final vocab GEMM on mma.sync m16n8k16 bf16, direct-lds fragments.
// Block tile 128x128, 8 warps (4m x 2n), warp tile 32x64.
// K=192 processed as 3 chunks of 64 (smem reload per chunk; acc persists).
// Smem: 512 (bias) + 2 * 128 rows * 72 elems * 2B = 37376 B < 48KB default.
// ---------------------------------------------------------------------------
#define FC_LDS   72                         // 64 + 8 pad bf16 per smem row

__global__ __launch_bounds__(256) void final_mma_kernel(
        const float* __restrict__ bf, float* __restrict__ out) {
    __shared__ float sBias[128];
    __shared__ __align__(16) __nv_bfloat16 sA[128 * FC_LDS];
    __shared__ __align__(16) __nv_bfloat16 sB[128 * FC_LDS];

    const int tid = threadIdx.x;
    const int m0 = blockIdx.x * 128;
    const int n0 = blockIdx.y * 128;

    if (tid < 128) sBias[tid] = bf[n0 + tid];

    const uint4* __restrict__ Ag = g_ybf + (long long)m0 * 24;
    const uint4* __restrict__ Bg = g_Wfb + (long long)n0 * 24;

    const int wid  = tid >> 5, lane = tid & 31;
    const int wm   = wid >> 1;            // 0..3  (m strip of 32)
    const int wn   = wid & 1;             // 0..1  (n strip of 64)
    const int l4   = lane >> 2;           // 0..7  groupID
    const int lm   = lane & 3;            // 0..3  threadID_in_group

    float acc[2][8][4];
#pragma unroll
    for (int mf = 0; mf < 2; mf++)
#pragma unroll
        for (int nf = 0; nf < 8; nf++)
#pragma unroll
            for (int c = 0; c < 4; c++) acc[mf][nf][c] = 0.0f;

#pragma unroll
    for (int ch = 0; ch < 3; ch++) {
        // Load chunk ch: uint4 columns [ch*8, ch*8+8) of each 128-row tile.
#pragma unroll
        for (int i = 0; i < 4; i++) {
            int idx = i * 256 + tid;          // 0..1023
            int r = idx >> 3, q = idx & 7;
            *(uint4*)(sA + r * FC_LDS + q * 8) = Ag[(long long)r * 24 + ch * 8 + q];
            *(uint4*)(sB + r * FC_LDS + q * 8) = Bg[(long long)r * 24 + ch * 8 + q];
        }
        __syncthreads();

#pragma unroll
        for (int ks = 0; ks < 4; ks++) {
            const int k0 = ks * 16;
            // A fragments: two 16x16 blocks (mf), rows wm*32 + mf*16 + ...
            uint32_t a[2][4];
#pragma unroll
            for (int mf = 0; mf < 2; mf++) {
                const __nv_bfloat16* base = sA + (wm * 32 + mf * 16 + l4) * FC_LDS + k0 + lm * 2;
                a[mf][0] = *(const uint32_t*)(base);
                a[mf][1] = *(const uint32_t*)(base + 8 * FC_LDS);
                a[mf][2] = *(const uint32_t*)(base + 8);
                a[mf][3] = *(const uint32_t*)(base + 8 * FC_LDS + 8);
            }
            // B fragments: 8 k16 x n8 blocks
            uint32_t b[8][2];
#pragma unroll
            for (int nf = 0; nf < 8; nf++) {
                const __nv_bfloat16* base = sB + (wn * 64 + nf * 8 + l4) * FC_LDS + k0 + lm * 2;
                b[nf][0] = *(const uint32_t*)(base);
                b[nf][1] = *(const uint32_t*)(base + 8);
            }
#pragma unroll
            for (int mf = 0; mf < 2; mf++)
#pragma unroll
                for (int nf = 0; nf < 8; nf++)
                    mma16816(acc[mf][nf], a[mf], b[nf]);
        }
        __syncthreads();
    }

    // Epilogue: add bias, store fp32.
#pragma unroll
    for (int mf = 0; mf < 2; mf++) {
        int row = m0 + wm * 32 + mf * 16 + l4;
        float* o0 = out + (long long)row * VOC + n0;
        float* o1 = out + (long long)(row + 8) * VOC + n0;
#pragma unroll
        for (int nf = 0; nf < 8; nf++) {
            int colr = wn * 64 + nf * 8 + lm * 2;
            float bx = sBias[colr], by = sBias[colr + 1];
            float2 v0 = make_float2(acc[mf][nf][0] + bx, acc[mf][nf][1] + by);
            float2 v1 = make_float2(acc[mf][nf][2] + bx, acc[mf][nf][3] + by);
            *(float2*)(o0 + colr) = v0;
            *(float2*)(o1 + colr) = v1;
        }
    }
}

// ---------------------------------------------------------------------------
extern "C" void kernel_launch(void* const* d_in, const int* in_sizes, int n_in,
                              void* d_out, int out_size) {
    (void)in_sizes; (void)n_in; (void)out_size;
    const int*   x   = (const int*)  d_in[0];
    const float* tok = (const float*)d_in[1];
    const float* pos = (const float*)d_in[2];
    const float* Wq  = (const float*)d_in[3];
    const float* bq  = (const float*)d_in[4];
    const float* Wk  = (const float*)d_in[5];
    const float* bk  = (const float*)d_in[6];
    const float* Wv  = (const float*)d_in[7];
    const float* bv  = (const float*)d_in[8];
    const float* Wo  = (const float*)d_in[9];
    const float* bo  = (const float*)d_in[10];
    const float* W1  = (const float*)d_in[11];
    const float* b1  = (const float*)d_in[12];
    const float* W2  = (const float*)d_in[13];
    const float* b2  = (const float*)d_in[14];
    const float* Wf  = (const float*)d_in[15];
    const float* bf  = (const float*)d_in[16];
    float* out = (float*)d_out;

    cudaFuncSetAttribute(attn_kernel, cudaFuncAttributeMaxDynamicSharedMemorySize, AT_SMEM);

    // Wf split is independent of everything else — kick it off first.
    split_wf_kernel<<<VOC / 128, 128>>>(Wf);

    embed_kernel<<<(NTOK * EDIM + 255) / 256, 256>>>(x, tok, pos);
    qkv_kernel<<<dim3(NTOK / 64, 2 * NH, 3), 256>>>(Wq, bq, Wk, bk, Wv, bv);
    attn_kernel<<<BATCH * NH, 256, AT_SMEM>>>();

    proj_o_part_kernel<<<dim3(NTOK / 64, 8), 256>>>(Wo);
    reduce_part_kernel<8, 0><<<(NTOK * EDIM + 255) / 256, 256>>>(bo);

    mlp1_kernel<<<dim3(NTOK / 64, MDIM / 64), 256>>>(W1, b1);

    mlp2_part_kernel<<<dim3(NTOK / 64, 4), 256>>>(W2);
    reduce_part_kernel<4, 1><<<(NTOK * EDIM + 255) / 256, 256>>>(b2);

    split_y_kernel<<<(NTOK * 96 + 255) / 256, 256>>>();

    final_mma_kernel<<<dim3(NTOK / 128, VOC / 128), 256>>>(bf, out);
}

// round 11
// speedup vs baseline: 1.8743x; 1.2743x over previous
#include <cuda_runtime.h>
#include <cuda_bf16.h>
#include <cuda_fp16.h>
#include <math.h>
#include <cstdint>

// Shapes
#define BATCH 64
#define TT    50
#define VOC   32000
#define EDIM  64
#define DH    128
#define NH    8
#define MDIM  256
#define NTOK  (BATCH*TT)      // 3200
#define HD    (NH*DH)         // 1024

// ---------------------------------------------------------------------------
// Scratch (no allocations allowed -> __device__ globals)
// ---------------------------------------------------------------------------
__device__ float g_h[NTOK*EDIM];
__device__ float g_Q[NTOK*HD];
__device__ float g_K[NTOK*HD];
__device__ float g_V[NTOK*HD];
__device__ float g_O[NTOK*HD];
__device__ float g_a[NTOK*EDIM];
__device__ float g_m[NTOK*MDIM];
__device__ float g_y[NTOK*EDIM];
__device__ float g_part[8*NTOK*EDIM];          // K-split partials
// Split-fp16 operands for the final vocab GEMM (fp16: 11-bit mantissa).
// A' row (per token): [hi(64) | lo(64)] fp16  -> 16 uint4
// B' row (per vocab): [hi(64)]          fp16  ->  8 uint4 (reused by both chunks)
// (hiA+loA)*hiB = A*hiB exactly; dropped term A*loB ~2^-11 relative.
__device__ uint4 g_ybf[NTOK*16];
__device__ uint4 g_Wfb[VOC*8];

// ---------------------------------------------------------------------------
// f32x2 packed math (FFMA2)
// ---------------------------------------------------------------------------
__device__ __forceinline__ unsigned long long pack2(float x, float y) {
    unsigned long long r;
    asm("mov.b64 %0, {%1, %2};" : "=l"(r) : "f"(x), "f"(y));
    return r;
}
__device__ __forceinline__ float2 unpack2(unsigned long long v) {
    float2 r;
    asm("mov.b64 {%0, %1}, %2;" : "=f"(r.x), "=f"(r.y) : "l"(v));
    return r;
}
__device__ __forceinline__ void ffma2(unsigned long long& d,
                                      unsigned long long a,
                                      unsigned long long b) {
    asm("fma.rn.f32x2 %0, %1, %2, %0;" : "+l"(d) : "l"(a), "l"(b));
}

__device__ __forceinline__ float act_apply(float v, int act) {
    if (act == 1) {
        v = 0.5f * v * (1.0f + erff(v * 0.70710678118654752f));
    }
    return v;
}

// ---------------------------------------------------------------------------
// Warp MMA fp16 (compute_80+; compiles at compute_103)
// ---------------------------------------------------------------------------
__device__ __forceinline__ void mma16816(float* d, const uint32_t* a, const uint32_t* b) {
    asm volatile("mma.sync.aligned.m16n8k16.row.col.f32.f16.f16.f32 "
        "{%0,%1,%2,%3}, {%4,%5,%6,%7}, {%8,%9}, {%0,%1,%2,%3};"
        : "+f"(d[0]), "+f"(d[1]), "+f"(d[2]), "+f"(d[3])
        : "r"(a[0]), "r"(a[1]), "r"(a[2]), "r"(a[3]), "r"(b[0]), "r"(b[1]));
}

// ---------------------------------------------------------------------------
// fp32x2 tile GEMM core: 64x64 tile, optional bias (nullptr -> 0), act.
// ---------------------------------------------------------------------------
__device__ void gemm64_core(const float* __restrict__ A, int lda,
                            const float* __restrict__ B, int ldb,
                            const float* __restrict__ bias,
                            float* __restrict__ C, int ldc,
                            int K, int act) {
    __shared__ float As[64][68];
    __shared__ float Bs[64][64];

    const int tid = threadIdx.x;
    const int tn  = (tid & 15) * 4;
    const int tm  = (tid >> 4) * 4;

    unsigned long long acc[4][2];
#pragma unroll
    for (int i = 0; i < 4; i++) { acc[i][0] = 0ull; acc[i][1] = 0ull; }

    for (int k0 = 0; k0 < K; k0 += 64) {
#pragma unroll
        for (int i = 0; i < 4; i++) {
            int idx = i * 256 + tid;
            int r = idx >> 4;
            int c = (idx & 15) * 4;
            float4 v = *(const float4*)(A + (long long)r * lda + k0 + c);
            *(float4*)&As[r][c] = v;
        }
#pragma unroll
        for (int i = 0; i < 4; i++) {
            int idx = i * 256 + tid;
            int r = idx >> 4;
            int c = (idx & 15) * 4;
            float4 v = *(const float4*)(B + (long long)(k0 + r) * ldb + c);
            *(float4*)&Bs[r][c] = v;
        }
        __syncthreads();

#pragma unroll 8
        for (int k = 0; k < 64; k++) {
            float a0 = As[tm + 0][k];
            float a1 = As[tm + 1][k];
            float a2 = As[tm + 2][k];
            float a3 = As[tm + 3][k];
            float4 b4 = *(const float4*)&Bs[k][tn];
            unsigned long long b01 = pack2(b4.x, b4.y);
            unsigned long long b23 = pack2(b4.z, b4.w);
            unsigned long long aa;
            aa = pack2(a0, a0); ffma2(acc[0][0], aa, b01); ffma2(acc[0][1], aa, b23);
            aa = pack2(a1, a1); ffma2(acc[1][0], aa, b01); ffma2(acc[1][1], aa, b23);
            aa = pack2(a2, a2); ffma2(acc[2][0], aa, b01); ffma2(acc[2][1], aa, b23);
            aa = pack2(a3, a3); ffma2(acc[3][0], aa, b01); ffma2(acc[3][1], aa, b23);
        }
        __syncthreads();
    }

    float4 bv4 = make_float4(0.f, 0.f, 0.f, 0.f);
    if (bias) bv4 = *(const float4*)(bias + tn);
#pragma unroll
    for (int i = 0; i < 4; i++) {
        float2 p0 = unpack2(acc[i][0]);
        float2 p1 = unpack2(acc[i][1]);
        float4 o;
        o.x = act_apply(p0.x + bv4.x, act);
        o.y = act_apply(p0.y + bv4.y, act);
        o.z = act_apply(p1.x + bv4.z, act);
        o.w = act_apply(p1.y + bv4.w, act);
        *(float4*)(C + (long long)(tm + i) * ldc + tn) = o;
    }
}

// ---------------------------------------------------------------------------
// Kernels
// ---------------------------------------------------------------------------
__global__ void embed_kernel(const int* __restrict__ x,
                             const float* __restrict__ tok,
                             const float* __restrict__ pos) {
    int i = blockIdx.x * 256 + threadIdx.x;
    if (i >= NTOK * EDIM) return;
    int m = i >> 6;
    int e = i & 63;
    int t = m % TT;
    int id = x[m];
    g_h[i] = tok[id * EDIM + e] + pos[t * EDIM + e];
}

__global__ void qkv_kernel(const float* __restrict__ Wq, const float* __restrict__ bq,
                           const float* __restrict__ Wk, const float* __restrict__ bk,
                           const float* __restrict__ Wv, const float* __restrict__ bv) {
    int m0   = blockIdx.x * 64;
    int head = blockIdx.y >> 1;
    int dt   = blockIdx.y & 1;
    const float* W; const float* bb; float* C;
    if (blockIdx.z == 0)      { W = Wq; bb = bq; C = g_Q; }
    else if (blockIdx.z == 1) { W = Wk; bb = bk; C = g_K; }
    else                      { W = Wv; bb = bv; C = g_V; }
    int n0 = head * DH + dt * 64;
    gemm64_core(g_h + (long long)m0 * EDIM, EDIM,
                W + head * EDIM * DH + dt * 64, DH,
                bb + n0,
                C + (long long)m0 * HD + n0, HD,
                EDIM, 0);
}

// ---------------------------------------------------------------------------
// Attention: one block per (b,h). Register-tiled micro-GEMMs.
// ---------------------------------------------------------------------------
#define AT_QT 0
#define AT_KT 8192
#define AT_V  16384
#define AT_S  22784
#define AT_SMEM (27136 * 4)

__global__ __launch_bounds__(256) void attn_kernel() {
    extern __shared__ float sm[];
    float* sQT = sm + AT_QT;
    float* sKT = sm + AT_KT;
    float* sV  = sm + AT_V;
    float* sS  = sm + AT_S;

    int bh = blockIdx.x;
    int b = bh >> 3, h = bh & 7;
    int tid = threadIdx.x;

    const float* Qb = g_Q + (long long)(b * TT) * HD + h * DH;
    const float* Kb = g_K + (long long)(b * TT) * HD + h * DH;
    const float* Vb = g_V + (long long)(b * TT) * HD + h * DH;

    for (int i = tid; i < 2048; i += 256) {      // 32 d4-groups x 64 t
        int d4 = i >> 6, t = i & 63;
        float4 q = make_float4(0.f, 0.f, 0.f, 0.f);
        float4 k = make_float4(0.f, 0.f, 0.f, 0.f);
        if (t < TT) {
            q = *(const float4*)(Qb + (long long)t * HD + d4 * 4);
            k = *(const float4*)(Kb + (long long)t * HD + d4 * 4);
        }
        int r = d4 * 4;
        sQT[(r + 0) * 64 + t] = q.x;
        sQT[(r + 1) * 64 + t] = q.y;
        sQT[(r + 2) * 64 + t] = q.z;
        sQT[(r + 3) * 64 + t] = q.w;
        sKT[(r + 0) * 64 + t] = k.x;
        sKT[(r + 1) * 64 + t] = k.y;
        sKT[(r + 2) * 64 + t] = k.z;
        sKT[(r + 3) * 64 + t] = k.w;
    }
    for (int i = tid; i < TT * 32; i += 256) {
        int s = i >> 5, c = i & 31;
        *(float4*)&sV[s * 128 + c * 4] = *(const float4*)(Vb + (long long)s * HD + c * 4);
    }
    __syncthreads();

    // Phase A: scores
    {
        const int tn = (tid & 15) * 4;   // s
        const int tm = (tid >> 4) * 4;   // t
        unsigned long long acc[4][2];
#pragma unroll
        for (int i = 0; i < 4; i++) { acc[i][0] = 0ull; acc[i][1] = 0ull; }

#pragma unroll 4
        for (int k = 0; k < 128; k++) {
            float4 q4 = *(const float4*)&sQT[k * 64 + tm];
            float4 k4 = *(const float4*)&sKT[k * 64 + tn];
            unsigned long long b01 = pack2(k4.x, k4.y);
            unsigned long long b23 = pack2(k4.z, k4.w);
            unsigned long long aa;
            aa = pack2(q4.x, q4.x); ffma2(acc[0][0], aa, b01); ffma2(acc[0][1], aa, b23);
            aa = pack2(q4.y, q4.y); ffma2(acc[1][0], aa, b01); ffma2(acc[1][1], aa, b23);
            aa = pack2(q4.z, q4.z); ffma2(acc[2][0], aa, b01); ffma2(acc[2][1], aa, b23);
            aa = pack2(q4.w, q4.w); ffma2(acc[3][0], aa, b01); ffma2(acc[3][1], aa, b23);
        }
        const float scale = 0.08838834764831845f;  // 1/sqrt(128)
#pragma unroll
        for (int i = 0; i < 4; i++) {
            float2 p0 = unpack2(acc[i][0]);
            float2 p1 = unpack2(acc[i][1]);
            float4 o = make_float4(p0.x * scale, p0.y * scale, p1.x * scale, p1.y * scale);
            *(float4*)&sS[(tm + i) * 68 + tn] = o;
        }
    }
    __syncthreads();

    // Softmax per row t (causal)
    if (tid < TT) {
        int t = tid;
        float* row = sS + t * 68;
        float mx = -1e30f;
        for (int s = 0; s <= t; s++) mx = fmaxf(mx, row[s]);
        float sum = 0.0f;
        for (int s = 0; s <= t; s++) { float e = expf(row[s] - mx); row[s] = e; sum += e; }
        float inv = 1.0f / sum;
        for (int s = 0; s <= t; s++) row[s] *= inv;
        for (int s = t + 1; s < TT; s++) row[s] = 0.0f;
    }
    __syncthreads();

    // Phase B: O = P*V
    {
        const int tm = (tid >> 5) * 8;   // t
        const int tn = (tid & 31) * 4;   // d
        unsigned long long acc[8][2];
#pragma unroll
        for (int i = 0; i < 8; i++) { acc[i][0] = 0ull; acc[i][1] = 0ull; }

#pragma unroll 2
        for (int s = 0; s < TT; s++) {
            float4 v4 = *(const float4*)&sV[s * 128 + tn];
            unsigned long long b01 = pack2(v4.x, v4.y);
            unsigned long long b23 = pack2(v4.z, v4.w);
#pragma unroll
            for (int i = 0; i < 8; i++) {
                float p = sS[(tm + i) * 68 + s];
                unsigned long long aa = pack2(p, p);
                ffma2(acc[i][0], aa, b01);
                ffma2(acc[i][1], aa, b23);
            }
        }

        float* Ob = g_O + (long long)(b * TT) * HD + h * DH;
#pragma unroll
        for (int i = 0; i < 8; i++) {
            int t = tm + i;
            if (t < TT) {
                float2 p0 = unpack2(acc[i][0]);
                float2 p1 = unpack2(acc[i][1]);
                float4 o = make_float4(p0.x, p0.y, p1.x, p1.y);
                *(float4*)(Ob + (long long)t * HD + tn) = o;
            }
        }
    }
}

// a-partials: K split 8x128.   grid (50, 8)
__global__ void proj_o_part_kernel(const float* __restrict__ Wo) {
    int m0 = blockIdx.x * 64;
    int ks = blockIdx.y;
    gemm64_core(g_O + (long long)m0 * HD + ks * 128, HD,
                Wo + (long long)ks * 128 * EDIM, EDIM, nullptr,
                g_part + (long long)ks * NTOK * EDIM + (long long)m0 * EDIM, EDIM,
                128, 0);
}
// y-partials: K split 4x64.    grid (50, 4)
__global__ void mlp2_part_kernel(const float* __restrict__ W2) {
    int m0 = blockIdx.x * 64;
    int ks = blockIdx.y;
    gemm64_core(g_m + (long long)m0 * MDIM + ks * 64, MDIM,
                W2 + (long long)ks * 64 * EDIM, EDIM, nullptr,
                g_part + (long long)ks * NTOK * EDIM + (long long)m0 * EDIM, EDIM,
                64, 0);
}
// Deterministic partial reduce + bias. DST selects the destination global in
// device code (never pass a __device__ symbol as a kernel arg from host).
template <int NSPLIT, int DST>   // DST: 0 -> g_a, 1 -> g_y
__global__ void reduce_part_kernel(const float* __restrict__ bias) {
    float* dst = (DST == 0) ? g_a : g_y;
    int i = blockIdx.x * 256 + threadIdx.x;
    if (i >= NTOK * EDIM) return;
    float s = bias[i & 63];
#pragma unroll
    for (int k = 0; k < NSPLIT; k++) s += g_part[(long long)k * NTOK * EDIM + i];
    dst[i] = s;
}

// m = gelu(a @ W1 + b1)       grid (50, 4)
__global__ void mlp1_kernel(const float* __restrict__ W1, const float* __restrict__ b1) {
    int m0 = blockIdx.x * 64;
    int n0 = blockIdx.y * 64;
    gemm64_core(g_a + (long long)m0 * EDIM, EDIM, W1 + n0, MDIM, b1 + n0,
                g_m + (long long)m0 * MDIM + n0, MDIM, EDIM, 1);
}

// ---------------------------------------------------------------------------
// Split-fp16 operand prep for final GEMM
// ---------------------------------------------------------------------------
__device__ __forceinline__ void split_fp16(float v, unsigned short& hi, unsigned short& lo) {
    __half h = __float2half(v);
    float r = v - __half2float(h);
    __half l = __float2half(r);
    hi = *reinterpret_cast<unsigned short*>(&h);
    lo = *reinterpret_cast<unsigned short*>(&l);
}

// A' = [hi(64) | lo(64)] per token row.  1 thread per output u32 (64 per row).
__global__ void split_y_kernel() {
    int i = blockIdx.x * 256 + threadIdx.x;
    if (i >= NTOK * 64) return;
    int r = i >> 6, j = i & 63;
    int jj = (j < 32) ? j : j - 32;
    bool lo_plane = (j >= 32);
    float v0 = g_y[r * 64 + 2 * jj];
    float v1 = g_y[r * 64 + 2 * jj + 1];
    unsigned short h0, l0, h1, l1;
    split_fp16(v0, h0, l0);
    split_fp16(v1, h1, l1);
    unsigned int w = lo_plane ? ((unsigned int)l0 | ((unsigned int)l1 << 16))
                              : ((unsigned int)h0 | ((unsigned int)h1 << 16));
    ((unsigned int*)g_ybf)[r * 64 + j] = w;
}

// B' = [hi(64)] per vocab row (fp16). Wf is [E][V] -> transpose via smem tile.
__global__ void split_wf_kernel(const float* __restrict__ Wf) {
    __shared__ unsigned short sH[128][68];
    int n0 = blockIdx.x * 128;
    int tid = threadIdx.x;  // 128
    for (int i = tid; i < 64 * 128; i += 128) {
        int e = i >> 7;
        int n = i & 127;
        float v = Wf[(long long)e * VOC + n0 + n];
        __half h = __float2half(v);
        sH[n][e] = *reinterpret_cast<unsigned short*>(&h);
    }
    __syncthreads();
    for (int i = tid; i < 128 * 32; i += 128) {
        int n = i >> 5, j = i & 31;
        unsigned int w = (unsigned int)sH[n][2*j] | ((unsigned int)sH[n][2*j+1] << 16);
        ((unsigned int*)g_Wfb)[(long long)(n0 + n) * 32 + j] = w;
    }
}

// ---------------------------------------------------------------------------
// Final vocab GEMM on mma.sync m16n8k16 fp16, direct-lds fragments.
// Block tile 128x128, 8 warps (4m x 2n), warp tile 32x64.
// K=128 as 2 A-chunks (hi, lo) x K=64; B (hi) loaded ONCE, reused by both.
// Smem: 512 + 2 * 128 * 72 * 2B = 37376 B < 48KB default.
// ---------------------------------------------------------------------------
#define FC_LDS   72                         // 64 + 8 pad fp16 per smem row

__global__ __launch_bounds__(256) void final_mma_kernel(
        const float* __restrict__ bf, float* __restrict__ out) {
    __shared__ float sBias[128];
    __shared__ __align__(16) __half sA[128 * FC_LDS];
    __shared__ __align__(16) __half sB[128 * FC_LDS];

    const int tid = threadIdx.x;
    const int m0 = blockIdx.x * 128;
    const int n0 = blockIdx.y * 128;

    if (tid < 128) sBias[tid] = bf[n0 + tid];

    const uint4* __restrict__ Ag = g_ybf + (long long)m0 * 16;
    const uint4* __restrict__ Bg = g_Wfb + (long long)n0 * 8;

    const int wid  = tid >> 5, lane = tid & 31;
    const int wm   = wid >> 1;            // 0..3  (m strip of 32)
    const int wn   = wid & 1;             // 0..1  (n strip of 64)
    const int l4   = lane >> 2;           // 0..7  groupID
    const int lm   = lane & 3;            // 0..3  threadID_in_group

    // Load B (once) and A chunk 0 (hi plane).
#pragma unroll
    for (int i = 0; i < 4; i++) {
        int idx = i * 256 + tid;          // 0..1023
        int r = idx >> 3, q = idx & 7;
        *(uint4*)(sB + r * FC_LDS + q * 8) = Bg[(long long)r * 8 + q];
        *(uint4*)(sA + r * FC_LDS + q * 8) = Ag[(long long)r * 16 + q];
    }
    __syncthreads();

    float acc[2][8][4];
#pragma unroll
    for (int mf = 0; mf < 2; mf++)
#pragma unroll
        for (int nf = 0; nf < 8; nf++)
#pragma unroll
            for (int c = 0; c < 4; c++) acc[mf][nf][c] = 0.0f;

#pragma unroll
    for (int ch = 0; ch < 2; ch++) {
#pragma unroll
        for (int ks = 0; ks < 4; ks++) {
            const int k0 = ks * 16;
            uint32_t a[2][4];
#pragma unroll
            for (int mf = 0; mf < 2; mf++) {
                const __half* base = sA + (wm * 32 + mf * 16 + l4) * FC_LDS + k0 + lm * 2;
                a[mf][0] = *(const uint32_t*)(base);
                a[mf][1] = *(const uint32_t*)(base + 8 * FC_LDS);
                a[mf][2] = *(const uint32_t*)(base + 8);
                a[mf][3] = *(const uint32_t*)(base + 8 * FC_LDS + 8);
            }
            uint32_t b[8][2];
#pragma unroll
            for (int nf = 0; nf < 8; nf++) {
                const __half* base = sB + (wn * 64 + nf * 8 + l4) * FC_LDS + k0 + lm * 2;
                b[nf][0] = *(const uint32_t*)(base);
                b[nf][1] = *(const uint32_t*)(base + 8);
            }
#pragma unroll
            for (int mf = 0; mf < 2; mf++)
#pragma unroll
                for (int nf = 0; nf < 8; nf++)
                    mma16816(acc[mf][nf], a[mf], b[nf]);
        }
        if (ch == 0) {
            // Swap in A chunk 1 (lo plane); B stays resident.
            __syncthreads();
#pragma unroll
            for (int i = 0; i < 4; i++) {
                int idx = i * 256 + tid;
                int r = idx >> 3, q = idx & 7;
                *(uint4*)(sA + r * FC_LDS + q * 8) = Ag[(long long)r * 16 + 8 + q];
            }
            __syncthreads();
        }
    }

    // Epilogue: add bias, store fp32.
#pragma unroll
    for (int mf = 0; mf < 2; mf++) {
        int row = m0 + wm * 32 + mf * 16 + l4;
        float* o0 = out + (long long)row * VOC + n0;
        float* o1 = out + (long long)(row + 8) * VOC + n0;
#pragma unroll
        for (int nf = 0; nf < 8; nf++) {
            int colr = wn * 64 + nf * 8 + lm * 2;
            float bx = sBias[colr], by = sBias[colr + 1];
            float2 v0 = make_float2(acc[mf][nf][0] + bx, acc[mf][nf][1] + by);
            float2 v1 = make_float2(acc[mf][nf][2] + bx, acc[mf][nf][3] + by);
            *(float2*)(o0 + colr) = v0;
            *(float2*)(o1 + colr) = v1;
        }
    }
}

// ---------------------------------------------------------------------------
extern "C" void kernel_launch(void* const* d_in, const int* in_sizes, int n_in,
                              void* d_out, int out_size) {
    (void)in_sizes; (void)n_in; (void)out_size;
    const int*   x   = (const int*)  d_in[0];
    const float* tok = (const float*)d_in[1];
    const float* pos = (const float*)d_in[2];
    const float* Wq  = (const float*)d_in[3];
    const float* bq  = (const float*)d_in[4];
    const float* Wk  = (const float*)d_in[5];
    const float* bk  = (const float*)d_in[6];
    const float* Wv  = (const float*)d_in[7];
    const float* bv  = (const float*)d_in[8];
    const float* Wo  = (const float*)d_in[9];
    const float* bo  = (const float*)d_in[10];
    const float* W1  = (const float*)d_in[11];
    const float* b1  = (const float*)d_in[12];
    const float* W2  = (const float*)d_in[13];
    const float* b2  = (const float*)d_in[14];
    const float* Wf  = (const float*)d_in[15];
    const float* bf  = (const float*)d_in[16];
    float* out = (float*)d_out;

    cudaFuncSetAttribute(attn_kernel, cudaFuncAttributeMaxDynamicSharedMemorySize, AT_SMEM);

    // Wf split is independent of everything else — kick it off first.
    split_wf_kernel<<<VOC / 128, 128>>>(Wf);

    embed_kernel<<<(NTOK * EDIM + 255) / 256, 256>>>(x, tok, pos);
    qkv_kernel<<<dim3(NTOK / 64, 2 * NH, 3), 256>>>(Wq, bq, Wk, bk, Wv, bv);
    attn_kernel<<<BATCH * NH, 256, AT_SMEM>>>();

    proj_o_part_kernel<<<dim3(NTOK / 64, 8), 256>>>(Wo);
    reduce_part_kernel<8, 0><<<(NTOK * EDIM + 255) / 256, 256>>>(bo);

    mlp1_kernel<<<dim3(NTOK / 64, MDIM / 64), 256>>>(W1, b1);

    mlp2_part_kernel<<<dim3(NTOK / 64, 4), 256>>>(W2);
    reduce_part_kernel<4, 1><<<(NTOK * EDIM + 255) / 256, 256>>>(b2);

    split_y_kernel<<<(NTOK * 64 + 255) / 256, 256>>>();

    final_mma_kernel<<<dim3(NTOK / 128, VOC / 128), 256>>>(bf, out);
}